// round 10
// baseline (speedup 1.0000x reference)
#include <cuda_runtime.h>
#include <cuda_fp16.h>
#include <math.h>
#include <stdint.h>

#define CB   512
#define CS   120
#define CD   216
#define CH   1024
#define CML  24

#define NCH   20        // 4 x-chunks (K 216->256 padded) + 16 h-chunks, K=64 each
#define NCH_X 4
#define NT    32        // N tiles of 128 cols (4 gates x 32 j)
#define MT    64        // M tile per CTA
#define XSTR  256       // padded x-plane stride
#define NK16  (NCH * 4) // 80 flat k16 steps

// A-only staging: 8KB per stage, 4 stages
#define ABUF 8192
#define SGJ 33
#define SMEM_STEP 33792   // max(4*8192=32768, sg 4*64*33*4=33792)

// ---------------- device globals ----------------
// W in B-fragment layout: uint4[ ((nt*4+gate)*NCH + ch)*4 + k16 ][64]  (lane*2 + {0,1})
__device__ __align__(16) uint4 g_Wfrag[(size_t)NT * 4 * NCH * 4 * 64];   // 10.5MB
__device__ __align__(16) __half g_src[(size_t)CS * CB * XSTR];
__device__ __align__(16) __half g_xd[(size_t)CB * XSTR];
__device__ __align__(16) __half g_h[2][(size_t)CB * CH];
__device__ float g_c[(size_t)CB * CH];
__device__ float g_bias[4 * CH];

// ---------------- helpers ----------------
__device__ __forceinline__ uint32_t smem_u32(const void* p) {
    uint32_t a;
    asm("{ .reg .u64 t; cvta.to.shared.u64 t, %1; cvt.u32.u64 %0, t; }" : "=r"(a) : "l"(p));
    return a;
}
__device__ __forceinline__ void ldsm4(uint32_t* r, uint32_t addr) {
    asm volatile("ldmatrix.sync.aligned.m8n8.x4.shared.b16 {%0,%1,%2,%3}, [%4];"
        : "=r"(r[0]), "=r"(r[1]), "=r"(r[2]), "=r"(r[3]) : "r"(addr));
}
__device__ __forceinline__ void mma_h(float* d, const uint32_t* a, uint32_t b0, uint32_t b1) {
    asm volatile("mma.sync.aligned.m16n8k16.row.col.f32.f16.f16.f32 "
        "{%0,%1,%2,%3}, {%4,%5,%6,%7}, {%8,%9}, {%0,%1,%2,%3};"
        : "+f"(d[0]), "+f"(d[1]), "+f"(d[2]), "+f"(d[3])
        : "r"(a[0]), "r"(a[1]), "r"(a[2]), "r"(a[3]), "r"(b0), "r"(b1));
}
#define CP16(dst, src) \
    asm volatile("cp.async.cg.shared.global [%0], [%1], 16;" :: "r"(dst), "l"(src))
#define CP_COMMIT() asm volatile("cp.async.commit_group;" ::: "memory")
#define CP_WAIT(n)  asm volatile("cp.async.wait_group %0;" :: "n"(n) : "memory")

__device__ __forceinline__ float sigf(float x) { return 1.0f / (1.0f + __expf(-x)); }

// ---------------- init / precompute ----------------
__global__ void init_kernel(const float* __restrict__ b_ih, const float* __restrict__ b_hh) {
    int idx = blockIdx.x * blockDim.x + threadIdx.x;
    if (idx < CB * CH) {
        g_c[idx] = 0.0f;
        g_h[0][idx] = __float2half_rn(0.0f);
    }
    if (idx < CB * XSTR) g_xd[idx] = __float2half_rn(0.0f);
    if (idx < 4 * CH) g_bias[idx] = b_ih[idx] + b_hh[idx];
}

__global__ void src_split_kernel(const float* __restrict__ src) {
    size_t idx = (size_t)blockIdx.x * blockDim.x + threadIdx.x;
    if (idx >= (size_t)CS * CB * XSTR) return;
    int c = (int)(idx & (XSTR - 1));
    int r = (int)((idx >> 8) & (CB - 1));
    int t = (int)(idx >> 17);
    float v = (c < CD) ? src[((size_t)r * CS + t) * CD + c] : 0.0f;
    g_src[idx] = __float2half_rn(v);
}

// W -> B-fragment layout (fp16). One thread per uint2 (4 fp16: k0,k1,k8,k9).
__global__ void prep_w_kernel(const float* __restrict__ W_ih, const float* __restrict__ W_hh) {
    int s = blockIdx.x * blockDim.x + threadIdx.x;
    const int TOT = NT * 4 * NCH * 4 * 128;   // 1,310,720 uint2s
    if (s >= TOT) return;
    int nb   = s & 3;
    int lane = (s >> 2) & 31;
    int k16  = (s >> 7) & 3;
    int rest = s >> 9;
    int ch = rest % NCH; rest /= NCH;
    int wc = rest & 3;          // gate
    int nt = rest >> 2;

    int j = nt * 32 + nb * 8 + (lane >> 2);
    int R = wc * CH + j;
    int k0 = k16 * 16 + (lane & 3) * 2;

    float v[4];
    if (ch < NCH_X) {
        int kb = ch * 64 + k0;
        int ks[4] = {kb, kb + 1, kb + 8, kb + 9};
#pragma unroll
        for (int q = 0; q < 4; ++q)
            v[q] = (ks[q] < CD) ? W_ih[(size_t)R * CD + ks[q]] : 0.0f;
    } else {
        const float* wr = W_hh + (size_t)R * CH + (ch - NCH_X) * 64 + k0;
        v[0] = wr[0]; v[1] = wr[1]; v[2] = wr[8]; v[3] = wr[9];
    }
    uint32_t lo = (uint32_t)__half_as_ushort(__float2half_rn(v[0])) |
                  ((uint32_t)__half_as_ushort(__float2half_rn(v[1])) << 16);
    uint32_t hi = (uint32_t)__half_as_ushort(__float2half_rn(v[2])) |
                  ((uint32_t)__half_as_ushort(__float2half_rn(v[3])) << 16);
    size_t dest = ((((size_t)(nt * 4 + wc) * NCH + ch) * 4 + k16)) * 128 + lane * 4 + nb;
    ((uint2*)g_Wfrag)[dest] = make_uint2(lo, hi);
}

// ---------------- fused LSTM step: pipelined A ldsm + W LDG ring ----------------
__global__ __launch_bounds__(256, 2)
void lstm_step(int use_xd, int t, int rd, int wr)
{
    extern __shared__ char smem[];
    const uint32_t sb = smem_u32(smem);
    const int tid = threadIdx.x;
    const int lane = tid & 31;
    const int w = tid >> 5;
    const int wm = w & 1;          // 2 row groups of 32
    const int wn = w >> 1;         // gate 0..3
    const int nt = blockIdx.x;
    const int mb = blockIdx.y * MT;

    const __half* xp = use_xd ? g_xd : (g_src + (size_t)t * CB * XSTR);
    const __half* hp = g_h[rd];

    // cp.async A mapping: 512 granules of 16B, 2 per thread (A region 8KB)
    int ar[2], acb[2];
    uint32_t aoff[2];
#pragma unroll
    for (int it = 0; it < 2; ++it) {
        int idx = tid + it * 256;
        ar[it]  = idx >> 3;        // 0..63
        acb[it] = idx & 7;
        aoff[it] = (uint32_t)(ar[it] * 128 + ((acb[it] ^ (ar[it] & 7)) << 4));
    }

    auto issue_chunk = [&](int ch, uint32_t buf) {
        const __half* p0;
        int stride, koff;
        if (ch < NCH_X) { p0 = xp; stride = XSTR; koff = ch * 64; }
        else            { p0 = hp; stride = CH;   koff = (ch - NCH_X) * 64; }
#pragma unroll
        for (int it = 0; it < 2; ++it) {
            const __half* sp = p0 + (size_t)(mb + ar[it]) * stride + koff + acb[it] * 8;
            CP16(buf + aoff[it], sp);
        }
    };

    // A ldsm base patterns (warp tile 32 rows x 32 cols)
    uint32_t abase[2]; int amask[2];
#pragma unroll
    for (int mg = 0; mg < 2; ++mg) {
        int rr = wm * 32 + mg * 16 + (lane & 15);
        abase[mg] = (uint32_t)(rr * 128);
        amask[mg] = rr & 7;
    }
    const int akc_half = lane >> 4;

    // flat-f A ldsm: stage from f>>2, kc from f&3
    uint32_t ah[2][2][4];   // [buf][mg][regs]
    auto prefetch_A = [&](int f, int b) {
        uint32_t buf = sb + (uint32_t)((f >> 2) & 3) * ABUF;
        uint32_t kc = (uint32_t)(2 * (f & 3) + akc_half);
#pragma unroll
        for (int mg = 0; mg < 2; ++mg)
            ldsm4(ah[b][mg], buf + abase[mg] + ((kc ^ (uint32_t)amask[mg]) << 4));
    };

    // W fragment pointer (uint4 units); consecutive flat k16 index strides 64 uint4s
    const uint4* wbase = g_Wfrag + ((size_t)(nt * 4 + wn) * NCH) * 4 * 64 + lane * 2;

    float acc[2][4][4];
#pragma unroll
    for (int mg = 0; mg < 2; ++mg)
#pragma unroll
        for (int nb = 0; nb < 4; ++nb)
#pragma unroll
            for (int e = 0; e < 4; ++e) acc[mg][nb][e] = 0.0f;

    // A prologue: 3 stages in flight
    issue_chunk(0, sb);            CP_COMMIT();
    issue_chunk(1, sb + ABUF);     CP_COMMIT();
    issue_chunk(2, sb + 2 * ABUF); CP_COMMIT();

    // W prologue: ring slots 0..2 <- flat k16 0..2
    uint4 wr0[4], wr1[4];
#pragma unroll
    for (int s = 0; s < 3; ++s) {
        const uint4* np = wbase + (size_t)s * 64;
        wr0[s] = __ldg(np); wr1[s] = __ldg(np + 1);
    }

    // first A fragment (f=0) after stage 0 lands
    CP_WAIT(2);
    __syncthreads();
    prefetch_A(0, 0);

    int cur = 0;
#pragma unroll 1
    for (int ch = 0; ch < NCH; ++ch) {
        CP_WAIT(1);        // stages ch and ch+1 complete
        __syncthreads();   // all warps done reading stage ch-1 (recycled below)
        if (ch + 3 < NCH) issue_chunk(ch + 3, sb + (uint32_t)((ch + 3) & 3) * ABUF);
        CP_COMMIT();   // empty group ok: keeps flight count constant

#pragma unroll
        for (int fi = 0; fi < 4; ++fi) {
            const int f = ch * 4 + fi;
            // W prefetch f+3 into free slot (fi+3)&3
            if (f + 3 < NK16) {
                const uint4* np = wbase + (size_t)(f + 3) * 64;
                wr0[(fi + 3) & 3] = __ldg(np);
                wr1[(fi + 3) & 3] = __ldg(np + 1);
            }
            // A prefetch f+1 into the other buffer (stage ch+1 ready at fi=3)
            if (f + 1 < NK16) prefetch_A(f + 1, cur ^ 1);

            // consume A buf 'cur' and W ring slot fi
            uint32_t b0[4] = {wr0[fi].x, wr0[fi].z, wr1[fi].x, wr1[fi].z};
            uint32_t b1[4] = {wr0[fi].y, wr0[fi].w, wr1[fi].y, wr1[fi].w};
#pragma unroll
            for (int mg = 0; mg < 2; ++mg)
#pragma unroll
                for (int nb = 0; nb < 4; ++nb)
                    mma_h(acc[mg][nb], ah[cur][mg], b0[nb], b1[nb]);
            cur ^= 1;
        }
    }
    __syncthreads();   // all ldsm consumption done before sg overwrite

    // gate exchange (reuse smem): sg[4 gates * 64 rows][SGJ]
    float* sg = (float*)smem;
#pragma unroll
    for (int mg = 0; mg < 2; ++mg)
#pragma unroll
        for (int nb = 0; nb < 4; ++nb) {
            int r0 = wm * 32 + mg * 16 + (lane >> 2);
            int jj = nb * 8 + (lane & 3) * 2;
            float* p0 = &sg[((size_t)(wn * 64 + r0)) * SGJ + jj];
            p0[0] = acc[mg][nb][0]; p0[1] = acc[mg][nb][1];
            float* p1 = p0 + 8 * SGJ;
            p1[0] = acc[mg][nb][2]; p1[1] = acc[mg][nb][3];
        }
    __syncthreads();

    // cell update: 64 rows x 32 j -> 256 threads x (1 row, 8 j)
    {
        int row = tid >> 2;
        int j0 = (tid & 3) * 8;
        int jcol = nt * 32 + j0;
        size_t off = (size_t)(mb + row) * CH + jcol;

        float gv[4][8];
#pragma unroll
        for (int g = 0; g < 4; ++g) {
            const float* p = &sg[((size_t)(g * 64 + row)) * SGJ + j0];
#pragma unroll
            for (int e = 0; e < 8; ++e) gv[g][e] = p[e] + g_bias[g * CH + jcol + e];
        }
        float4 cA = *(const float4*)(g_c + off);
        float4 cB = *(const float4*)(g_c + off + 4);
        float cold[8] = {cA.x, cA.y, cA.z, cA.w, cB.x, cB.y, cB.z, cB.w};
        float cn[8], hn[8];
#pragma unroll
        for (int e = 0; e < 8; ++e) {
            float ci = sigf(gv[0][e]);
            float cf = sigf(gv[1][e]);
            float cg = tanhf(gv[2][e]);
            float co = sigf(gv[3][e]);
            cn[e] = cf * cold[e] + ci * cg;
            hn[e] = co * tanhf(cn[e]);
        }
        *(float4*)(g_c + off)     = make_float4(cn[0], cn[1], cn[2], cn[3]);
        *(float4*)(g_c + off + 4) = make_float4(cn[4], cn[5], cn[6], cn[7]);

        uint32_t ph[4];
#pragma unroll
        for (int e2 = 0; e2 < 4; ++e2) {
            __half ha = __float2half_rn(hn[e2 * 2]);
            __half hb = __float2half_rn(hn[e2 * 2 + 1]);
            ph[e2] = (uint32_t)__half_as_ushort(ha) | ((uint32_t)__half_as_ushort(hb) << 16);
        }
        *(uint4*)(&g_h[wr][off]) = make_uint4(ph[0], ph[1], ph[2], ph[3]);
    }
}

// ---------------- decoder projection ----------------
__global__ __launch_bounds__(256)
void proj_kernel(int hbuf,
                 const float* __restrict__ W_out,
                 const float* __restrict__ b_out,
                 float* __restrict__ outp)
{
    int lane = threadIdx.x & 31;
    int w = threadIdx.x >> 5;
    int d = blockIdx.x * 8 + w;
    int r0 = blockIdx.y * 8;
    const __half* hp = g_h[hbuf];
    int k0 = lane * 32;

    float wv[32];
    {
        const float4* wp = (const float4*)(W_out + (size_t)d * CH + k0);
#pragma unroll
        for (int q = 0; q < 8; ++q) {
            float4 f = wp[q];
            wv[q * 4 + 0] = f.x; wv[q * 4 + 1] = f.y; wv[q * 4 + 2] = f.z; wv[q * 4 + 3] = f.w;
        }
    }
    float acc[8];
#pragma unroll
    for (int r = 0; r < 8; ++r) {
        const uint4* hq = (const uint4*)(hp + (size_t)(r0 + r) * CH + k0);
        float s = 0.0f;
#pragma unroll
        for (int q = 0; q < 4; ++q) {
            uint4 hv = hq[q];
            const __half2* h2 = (const __half2*)&hv;
#pragma unroll
            for (int e = 0; e < 4; ++e) {
                float2 a = __half22float2(h2[e]);
                int kk = q * 8 + e * 2;
                s += a.x * wv[kk] + a.y * wv[kk + 1];
            }
        }
        acc[r] = s;
    }
#pragma unroll
    for (int r = 0; r < 8; ++r) {
#pragma unroll
        for (int off = 16; off > 0; off >>= 1)
            acc[r] += __shfl_xor_sync(0xFFFFFFFFu, acc[r], off);
    }
    if (lane == 0) {
        float bo = b_out[d];
#pragma unroll
        for (int r = 0; r < 8; ++r) {
            float y = acc[r] + bo;
            int row = r0 + r;
            outp[(size_t)row * CML * CD + d] = y;
            g_xd[(size_t)row * XSTR + d] = __float2half_rn(y);
        }
    }
}

extern "C" void kernel_launch(void* const* d_in, const int* in_sizes, int n_in,
                              void* d_out, int out_size)
{
    (void)in_sizes; (void)n_in; (void)out_size;
    const float* src   = (const float*)d_in[0];
    const float* W_ih  = (const float*)d_in[1];
    const float* W_hh  = (const float*)d_in[2];
    const float* b_ih  = (const float*)d_in[3];
    const float* b_hh  = (const float*)d_in[4];
    const float* W_out = (const float*)d_in[5];
    const float* b_out = (const float*)d_in[6];
    float* out = (float*)d_out;

    static int once = 0;
    if (!once) {
        cudaFuncSetAttribute(lstm_step, cudaFuncAttributeMaxDynamicSharedMemorySize, SMEM_STEP);
        once = 1;
    }

    init_kernel<<<(CB * CH + 255) / 256, 256>>>(b_ih, b_hh);
    {
        size_t tot = (size_t)CS * CB * XSTR;
        src_split_kernel<<<(unsigned)((tot + 255) / 256), 256>>>(src);
    }
    {
        int tot = NT * 4 * NCH * 4 * 128;
        prep_w_kernel<<<(tot + 255) / 256, 256>>>(W_ih, W_hh);
    }

    dim3 sgrid(NT, CB / MT);   // 32 x 8 = 256 CTAs
    dim3 pgrid(27, CB / 8);    // 27 x 64

    int p = 0;
    for (int t = 0; t < CS; ++t) {
        lstm_step<<<sgrid, 256, SMEM_STEP>>>(0, t, p, p ^ 1);
        p ^= 1;
    }
    for (int s = 0; s < CML; ++s) {
        if (s == 0) lstm_step<<<sgrid, 256, SMEM_STEP>>>(0, CS - 1, p, p ^ 1);
        else        lstm_step<<<sgrid, 256, SMEM_STEP>>>(1, 0, p, p ^ 1);
        proj_kernel<<<pgrid, 256>>>(p ^ 1, W_out, b_out, out + (size_t)s * CD);
        p ^= 1;
    }
}

// round 11
// speedup vs baseline: 1.6125x; 1.6125x over previous
#include <cuda_runtime.h>
#include <cuda_fp16.h>
#include <math.h>
#include <stdint.h>

#define CB   512
#define CS   120
#define CD   216
#define CH   1024
#define CML  24

#define NCH   20        // 4 x-chunks (K 216->256 padded) + 16 h-chunks, K=64 each
#define NCH_X 4
#define NT    32        // N tiles of 128 cols (4 gates x 32 j)
#define MT    128       // M tile per CTA
#define XSTR  256       // padded x-plane stride

// stage: A 16KB | W 16KB, double buffered
#define BUF_STRIDE 32768
#define SGJ 33
#define SMEM_STEP (4 * 128 * SGJ * 4)   // 67584 >= 2*BUF_STRIDE=65536

// ---------------- device globals ----------------
__device__ __align__(16) __half g_Wimg[(size_t)NT * NCH * 8192];   // 10.5MB swizzled fp16 W
__device__ __align__(16) __half g_src[(size_t)CS * CB * XSTR];
__device__ __align__(16) __half g_xd[(size_t)CB * XSTR];
__device__ __align__(16) __half g_h[2][(size_t)CB * CH];
__device__ float g_c[(size_t)CB * CH];
__device__ float g_bias[4 * CH];

// ---------------- helpers ----------------
__device__ __forceinline__ uint32_t smem_u32(const void* p) {
    uint32_t a;
    asm("{ .reg .u64 t; cvta.to.shared.u64 t, %1; cvt.u32.u64 %0, t; }" : "=r"(a) : "l"(p));
    return a;
}
__device__ __forceinline__ void ldsm4(uint32_t* r, uint32_t addr) {
    asm volatile("ldmatrix.sync.aligned.m8n8.x4.shared.b16 {%0,%1,%2,%3}, [%4];"
        : "=r"(r[0]), "=r"(r[1]), "=r"(r[2]), "=r"(r[3]) : "r"(addr));
}
__device__ __forceinline__ void mma_h(float* d, const uint32_t* a, uint32_t b0, uint32_t b1) {
    asm volatile("mma.sync.aligned.m16n8k16.row.col.f32.f16.f16.f32 "
        "{%0,%1,%2,%3}, {%4,%5,%6,%7}, {%8,%9}, {%0,%1,%2,%3};"
        : "+f"(d[0]), "+f"(d[1]), "+f"(d[2]), "+f"(d[3])
        : "r"(a[0]), "r"(a[1]), "r"(a[2]), "r"(a[3]), "r"(b0), "r"(b1));
}
#define CP16(dst, src) \
    asm volatile("cp.async.cg.shared.global [%0], [%1], 16;" :: "r"(dst), "l"(src))
#define CP_COMMIT() asm volatile("cp.async.commit_group;" ::: "memory")
#define CP_WAIT(n)  asm volatile("cp.async.wait_group %0;" :: "n"(n) : "memory")

__device__ __forceinline__ float sigf(float x) { return 1.0f / (1.0f + __expf(-x)); }

// ---------------- init / precompute ----------------
__global__ void init_kernel(const float* __restrict__ b_ih, const float* __restrict__ b_hh) {
    int idx = blockIdx.x * blockDim.x + threadIdx.x;
    if (idx < CB * CH) {
        g_c[idx] = 0.0f;
        g_h[0][idx] = __float2half_rn(0.0f);
    }
    if (idx < CB * XSTR) g_xd[idx] = __float2half_rn(0.0f);
    if (idx < 4 * CH) g_bias[idx] = b_ih[idx] + b_hh[idx];
}

__global__ void src_split_kernel(const float* __restrict__ src) {
    size_t idx = (size_t)blockIdx.x * blockDim.x + threadIdx.x;
    if (idx >= (size_t)CS * CB * XSTR) return;
    int c = (int)(idx & (XSTR - 1));
    int r = (int)((idx >> 8) & (CB - 1));
    int t = (int)(idx >> 17);
    float v = (c < CD) ? src[((size_t)r * CS + t) * CD + c] : 0.0f;
    g_src[idx] = __float2half_rn(v);
}

// W -> pre-swizzled fp16 tile image: [nt][ch] tiles of 128 n-rows x 64 k
__global__ void prep_w_kernel(const float* __restrict__ W_ih, const float* __restrict__ W_hh) {
    int idx = blockIdx.x * blockDim.x + threadIdx.x;
    const int TOT = NT * NCH * 128 * 64;
    if (idx >= TOT) return;
    int k = idx & 63;
    int r = (idx >> 6) & 127;
    int ch = (idx >> 13) % NCH;
    int nt = idx / (NCH * 8192);
    int gate = r >> 5, jj = r & 31;
    int R = gate * CH + nt * 32 + jj;
    float v;
    if (ch < NCH_X) {
        int kg = ch * 64 + k;
        v = (kg < CD) ? W_ih[(size_t)R * CD + kg] : 0.0f;
    } else {
        v = W_hh[(size_t)R * CH + (ch - NCH_X) * 64 + k];
    }
    size_t dest = (size_t)(nt * NCH + ch) * 8192 + r * 64 + (((k >> 3) ^ (r & 7)) << 3) + (k & 7);
    g_Wimg[dest] = __float2half_rn(v);
}

// ---------------- fused LSTM step: 8 warps, warp tile 64x32 (R4 structure, 1-term) ----------------
__global__ __launch_bounds__(256, 1)
void lstm_step(int use_xd, int t, int rd, int wr)
{
    extern __shared__ char smem[];
    const uint32_t sb = smem_u32(smem);
    const int tid = threadIdx.x;
    const int lane = tid & 31;
    const int w = tid >> 5;
    const int wm = w & 1;          // 2 warp rows (64 each)
    const int wn = w >> 1;         // 4 warp cols = gate
    const int nt = blockIdx.x;
    const int mb = blockIdx.y * MT;

    const __half* xp = use_xd ? g_xd : (g_src + (size_t)t * CB * XSTR);
    const __half* hp = g_h[rd];

    // cp.async A mapping: 1024 granules of 16B, 4 per thread (A region 16KB)
    int ar[4], acb[4];
    uint32_t aoff[4];
#pragma unroll
    for (int it = 0; it < 4; ++it) {
        int idx = tid + it * 256;
        ar[it]  = idx >> 3;        // 0..127
        acb[it] = idx & 7;
        aoff[it] = (uint32_t)(ar[it] * 128 + ((acb[it] ^ (ar[it] & 7)) << 4));
    }

    auto issue_chunk = [&](int ch, uint32_t buf) {
        const char* wsrc = (const char*)(g_Wimg + (size_t)(nt * NCH + ch) * 8192);
#pragma unroll
        for (int it = 0; it < 4; ++it) {
            int g = tid + it * 256;
            CP16(buf + 16384 + g * 16, wsrc + g * 16);
        }
        const __half* p0;
        int stride, koff;
        if (ch < NCH_X) { p0 = xp; stride = XSTR; koff = ch * 64; }
        else            { p0 = hp; stride = CH;   koff = (ch - NCH_X) * 64; }
#pragma unroll
        for (int it = 0; it < 4; ++it) {
            const __half* sp = p0 + (size_t)(mb + ar[it]) * stride + koff + acb[it] * 8;
            CP16(buf + aoff[it], sp);
        }
    };

    // ldmatrix base patterns
    uint32_t abase[4]; int amask[4];
#pragma unroll
    for (int mg = 0; mg < 4; ++mg) {
        int rr = wm * 64 + mg * 16 + (lane & 15);
        abase[mg] = (uint32_t)(rr * 128);
        amask[mg] = rr & 7;
    }
    const int akc_half = lane >> 4;
    uint32_t wbse[2]; int wmask[2];
#pragma unroll
    for (int p16 = 0; p16 < 2; ++p16) {
        int rr = wn * 32 + p16 * 16 + (lane & 7) + ((lane >> 4) << 3);
        wbse[p16] = (uint32_t)(16384 + rr * 128);
        wmask[p16] = rr & 7;
    }
    const int wkc_par = (lane >> 3) & 1;

    float acc[4][4][4];
#pragma unroll
    for (int mg = 0; mg < 4; ++mg)
#pragma unroll
        for (int nb = 0; nb < 4; ++nb)
#pragma unroll
            for (int e = 0; e < 4; ++e) acc[mg][nb][e] = 0.0f;

    issue_chunk(0, sb);
    CP_COMMIT();

#pragma unroll 1
    for (int ch = 0; ch < NCH; ++ch) {
        const uint32_t buf = sb + (uint32_t)(ch & 1) * BUF_STRIDE;
        if (ch + 1 < NCH) {
            issue_chunk(ch + 1, sb + (uint32_t)((ch + 1) & 1) * BUF_STRIDE);
            CP_COMMIT();
            CP_WAIT(1);
        } else {
            CP_WAIT(0);
        }
        __syncthreads();

#pragma unroll
        for (int k16 = 0; k16 < 4; ++k16) {
            uint32_t ah[4][4], wf[2][4];
            const uint32_t kcA = (uint32_t)(2 * k16 + akc_half);
            const uint32_t kcW = (uint32_t)(2 * k16 + wkc_par);
#pragma unroll
            for (int p16 = 0; p16 < 2; ++p16)
                ldsm4(wf[p16], buf + wbse[p16] + ((kcW ^ (uint32_t)wmask[p16]) << 4));
#pragma unroll
            for (int mg = 0; mg < 4; ++mg)
                ldsm4(ah[mg], buf + abase[mg] + ((kcA ^ (uint32_t)amask[mg]) << 4));
#pragma unroll
            for (int mg = 0; mg < 4; ++mg)
#pragma unroll
                for (int p16 = 0; p16 < 2; ++p16) {
                    mma_h(acc[mg][2 * p16 + 0], ah[mg], wf[p16][0], wf[p16][1]);
                    mma_h(acc[mg][2 * p16 + 1], ah[mg], wf[p16][2], wf[p16][3]);
                }
        }
        __syncthreads();
    }

    // gate exchange (reuse smem)
    float* sg = (float*)smem;
#pragma unroll
    for (int mg = 0; mg < 4; ++mg)
#pragma unroll
        for (int nb = 0; nb < 4; ++nb) {
            int r0 = wm * 64 + mg * 16 + (lane >> 2);
            int jj = nb * 8 + (lane & 3) * 2;
            float* p0 = &sg[((size_t)(wn * 128 + r0)) * SGJ + jj];
            p0[0] = acc[mg][nb][0]; p0[1] = acc[mg][nb][1];
            float* p1 = p0 + 8 * SGJ;
            p1[0] = acc[mg][nb][2]; p1[1] = acc[mg][nb][3];
        }
    __syncthreads();

    // cell update: 128 rows x 32 j -> 256 threads x 2 units of (1 row, 8 j)
    __half* hw = g_h[wr];
#pragma unroll
    for (int u = 0; u < 2; ++u) {
        int uid = tid + u * 256;
        int row = uid >> 2;
        int j0 = (uid & 3) * 8;
        int jcol = nt * 32 + j0;
        size_t off = (size_t)(mb + row) * CH + jcol;

        float gv[4][8];
#pragma unroll
        for (int g = 0; g < 4; ++g) {
            const float* p = &sg[((size_t)(g * 128 + row)) * SGJ + j0];
#pragma unroll
            for (int e = 0; e < 8; ++e) gv[g][e] = p[e] + g_bias[g * CH + jcol + e];
        }
        float4 cA = *(const float4*)(g_c + off);
        float4 cB = *(const float4*)(g_c + off + 4);
        float cold[8] = {cA.x, cA.y, cA.z, cA.w, cB.x, cB.y, cB.z, cB.w};
        float cn[8], hn[8];
#pragma unroll
        for (int e = 0; e < 8; ++e) {
            float ci = sigf(gv[0][e]);
            float cf = sigf(gv[1][e]);
            float cg = tanhf(gv[2][e]);
            float co = sigf(gv[3][e]);
            cn[e] = cf * cold[e] + ci * cg;
            hn[e] = co * tanhf(cn[e]);
        }
        *(float4*)(g_c + off)     = make_float4(cn[0], cn[1], cn[2], cn[3]);
        *(float4*)(g_c + off + 4) = make_float4(cn[4], cn[5], cn[6], cn[7]);

        uint32_t ph[4];
#pragma unroll
        for (int e2 = 0; e2 < 4; ++e2) {
            __half ha = __float2half_rn(hn[e2 * 2]);
            __half hb = __float2half_rn(hn[e2 * 2 + 1]);
            ph[e2] = (uint32_t)__half_as_ushort(ha) | ((uint32_t)__half_as_ushort(hb) << 16);
        }
        *(uint4*)(hw + off) = make_uint4(ph[0], ph[1], ph[2], ph[3]);
    }
}

// ---------------- decoder projection ----------------
__global__ __launch_bounds__(256)
void proj_kernel(int hbuf,
                 const float* __restrict__ W_out,
                 const float* __restrict__ b_out,
                 float* __restrict__ outp)
{
    int lane = threadIdx.x & 31;
    int w = threadIdx.x >> 5;
    int d = blockIdx.x * 8 + w;
    int r0 = blockIdx.y * 8;
    const __half* hp = g_h[hbuf];
    int k0 = lane * 32;

    float wv[32];
    {
        const float4* wp = (const float4*)(W_out + (size_t)d * CH + k0);
#pragma unroll
        for (int q = 0; q < 8; ++q) {
            float4 f = wp[q];
            wv[q * 4 + 0] = f.x; wv[q * 4 + 1] = f.y; wv[q * 4 + 2] = f.z; wv[q * 4 + 3] = f.w;
        }
    }
    float acc[8];
#pragma unroll
    for (int r = 0; r < 8; ++r) {
        const uint4* hq = (const uint4*)(hp + (size_t)(r0 + r) * CH + k0);
        float s = 0.0f;
#pragma unroll
        for (int q = 0; q < 4; ++q) {
            uint4 hv = hq[q];
            const __half2* h2 = (const __half2*)&hv;
#pragma unroll
            for (int e = 0; e < 4; ++e) {
                float2 a = __half22float2(h2[e]);
                int kk = q * 8 + e * 2;
                s += a.x * wv[kk] + a.y * wv[kk + 1];
            }
        }
        acc[r] = s;
    }
#pragma unroll
    for (int r = 0; r < 8; ++r) {
#pragma unroll
        for (int off = 16; off > 0; off >>= 1)
            acc[r] += __shfl_xor_sync(0xFFFFFFFFu, acc[r], off);
    }
    if (lane == 0) {
        float bo = b_out[d];
#pragma unroll
        for (int r = 0; r < 8; ++r) {
            float y = acc[r] + bo;
            int row = r0 + r;
            outp[(size_t)row * CML * CD + d] = y;
            g_xd[(size_t)row * XSTR + d] = __float2half_rn(y);
        }
    }
}

extern "C" void kernel_launch(void* const* d_in, const int* in_sizes, int n_in,
                              void* d_out, int out_size)
{
    (void)in_sizes; (void)n_in; (void)out_size;
    const float* src   = (const float*)d_in[0];
    const float* W_ih  = (const float*)d_in[1];
    const float* W_hh  = (const float*)d_in[2];
    const float* b_ih  = (const float*)d_in[3];
    const float* b_hh  = (const float*)d_in[4];
    const float* W_out = (const float*)d_in[5];
    const float* b_out = (const float*)d_in[6];
    float* out = (float*)d_out;

    static int once = 0;
    if (!once) {
        cudaFuncSetAttribute(lstm_step, cudaFuncAttributeMaxDynamicSharedMemorySize, SMEM_STEP);
        once = 1;
    }

    init_kernel<<<(CB * CH + 255) / 256, 256>>>(b_ih, b_hh);
    {
        size_t tot = (size_t)CS * CB * XSTR;
        src_split_kernel<<<(unsigned)((tot + 255) / 256), 256>>>(src);
    }
    {
        int tot = NT * NCH * 128 * 64;
        prep_w_kernel<<<(tot + 255) / 256, 256>>>(W_ih, W_hh);
    }

    dim3 sgrid(NT, CB / MT);   // 32 x 4 = 128 CTAs
    dim3 pgrid(27, CB / 8);    // 27 x 64

    int p = 0;
    for (int t = 0; t < CS; ++t) {
        lstm_step<<<sgrid, 256, SMEM_STEP>>>(0, t, p, p ^ 1);
        p ^= 1;
    }
    for (int s = 0; s < CML; ++s) {
        if (s == 0) lstm_step<<<sgrid, 256, SMEM_STEP>>>(0, CS - 1, p, p ^ 1);
        else        lstm_step<<<sgrid, 256, SMEM_STEP>>>(1, 0, p, p ^ 1);
        proj_kernel<<<pgrid, 256>>>(p ^ 1, W_out, b_out, out + (size_t)s * CD);
        p ^= 1;
    }
}

// round 12
// speedup vs baseline: 1.6527x; 1.0249x over previous
#include <cuda_runtime.h>
#include <cuda_fp16.h>
#include <math.h>
#include <stdint.h>

#define CB   512
#define CS   120
#define CD   216
#define CH   1024
#define CML  24

#define NCH   10        // 2 x-chunks (K 216->256 padded) + 8 h-chunks, K=128 each
#define NCH_X 2
#define NT    32        // N tiles of 128 cols (4 gates x 32 j)
#define MT    64        // M tile per CTA
#define XSTR  256       // padded x-plane stride
#define NK16  80        // flat k16 steps (16 x + 64 h)

// A staging: 64 rows x 128 cols fp16 = 16KB per stage, 3 stages
#define ABUF 16384
#define SGJ 33
#define SMEM_STEP (3 * ABUF)   // 49152 ; sg (4*64*33*4=33792) reuses it

// ---------------- device globals ----------------
// W in B-fragment layout: flat k16 f=0..79, uint4[ (nt*4+gate)*80 + f ][64]
__device__ __align__(16) uint4 g_Wfrag[(size_t)NT * 4 * NK16 * 64];   // 10.5MB
__device__ __align__(16) __half g_src[(size_t)CS * CB * XSTR];
__device__ __align__(16) __half g_xd[(size_t)CB * XSTR];
__device__ __align__(16) __half g_h[2][(size_t)CB * CH];
__device__ float g_c[(size_t)CB * CH];
__device__ float g_bias[4 * CH];

// ---------------- helpers ----------------
__device__ __forceinline__ uint32_t smem_u32(const void* p) {
    uint32_t a;
    asm("{ .reg .u64 t; cvta.to.shared.u64 t, %1; cvt.u32.u64 %0, t; }" : "=r"(a) : "l"(p));
    return a;
}
__device__ __forceinline__ void ldsm4(uint32_t* r, uint32_t addr) {
    asm volatile("ldmatrix.sync.aligned.m8n8.x4.shared.b16 {%0,%1,%2,%3}, [%4];"
        : "=r"(r[0]), "=r"(r[1]), "=r"(r[2]), "=r"(r[3]) : "r"(addr));
}
__device__ __forceinline__ void mma_h(float* d, const uint32_t* a, uint32_t b0, uint32_t b1) {
    asm volatile("mma.sync.aligned.m16n8k16.row.col.f32.f16.f16.f32 "
        "{%0,%1,%2,%3}, {%4,%5,%6,%7}, {%8,%9}, {%0,%1,%2,%3};"
        : "+f"(d[0]), "+f"(d[1]), "+f"(d[2]), "+f"(d[3])
        : "r"(a[0]), "r"(a[1]), "r"(a[2]), "r"(a[3]), "r"(b0), "r"(b1));
}
#define CP16(dst, src) \
    asm volatile("cp.async.cg.shared.global [%0], [%1], 16;" :: "r"(dst), "l"(src))
#define CP_COMMIT() asm volatile("cp.async.commit_group;" ::: "memory")
#define CP_WAIT(n)  asm volatile("cp.async.wait_group %0;" :: "n"(n) : "memory")

__device__ __forceinline__ float sigf(float x) { return 1.0f / (1.0f + __expf(-x)); }

// ---------------- init / precompute ----------------
__global__ void init_kernel(const float* __restrict__ b_ih, const float* __restrict__ b_hh) {
    int idx = blockIdx.x * blockDim.x + threadIdx.x;
    if (idx < CB * CH) {
        g_c[idx] = 0.0f;
        g_h[0][idx] = __float2half_rn(0.0f);
    }
    if (idx < CB * XSTR) g_xd[idx] = __float2half_rn(0.0f);
    if (idx < 4 * CH) g_bias[idx] = b_ih[idx] + b_hh[idx];
}

__global__ void src_split_kernel(const float* __restrict__ src) {
    size_t idx = (size_t)blockIdx.x * blockDim.x + threadIdx.x;
    if (idx >= (size_t)CS * CB * XSTR) return;
    int c = (int)(idx & (XSTR - 1));
    int r = (int)((idx >> 8) & (CB - 1));
    int t = (int)(idx >> 17);
    float v = (c < CD) ? src[((size_t)r * CS + t) * CD + c] : 0.0f;
    g_src[idx] = __float2half_rn(v);
}

// W -> B-fragment layout (fp16), flat k16 index. One thread per uint2.
__global__ void prep_w_kernel(const float* __restrict__ W_ih, const float* __restrict__ W_hh) {
    int s = blockIdx.x * blockDim.x + threadIdx.x;
    const int TOT = NT * 4 * NK16 * 128;
    if (s >= TOT) return;
    int nb   = s & 3;
    int lane = (s >> 2) & 31;
    int rest = s >> 7;
    int f  = rest % NK16; rest /= NK16;   // flat k16 0..79 (0..15 x, 16..79 h)
    int wc = rest & 3;                    // gate
    int nt = rest >> 2;

    int j = nt * 32 + nb * 8 + (lane >> 2);
    int R = wc * CH + j;
    int k0 = f * 16 + (lane & 3) * 2;     // global k within [x(256-pad) | h(1024)]

    float v[4];
    if (f < 16) {
        int ks[4] = {k0, k0 + 1, k0 + 8, k0 + 9};
#pragma unroll
        for (int q = 0; q < 4; ++q)
            v[q] = (ks[q] < CD) ? W_ih[(size_t)R * CD + ks[q]] : 0.0f;
    } else {
        const float* wr = W_hh + (size_t)R * CH + (k0 - 256);
        v[0] = wr[0]; v[1] = wr[1]; v[2] = wr[8]; v[3] = wr[9];
    }
    uint32_t lo = (uint32_t)__half_as_ushort(__float2half_rn(v[0])) |
                  ((uint32_t)__half_as_ushort(__float2half_rn(v[1])) << 16);
    uint32_t hi = (uint32_t)__half_as_ushort(__float2half_rn(v[2])) |
                  ((uint32_t)__half_as_ushort(__float2half_rn(v[3])) << 16);
    size_t dest = (((size_t)(nt * 4 + wc) * NK16 + f)) * 128 + lane * 4 + nb;
    ((uint2*)g_Wfrag)[dest] = make_uint2(lo, hi);
}

// ---------------- fused LSTM step: K-chunk 128, within-chunk A pipeline ----------------
__global__ __launch_bounds__(256, 2)
void lstm_step(int use_xd, int t, int rd, int wr)
{
    extern __shared__ char smem[];
    const uint32_t sb = smem_u32(smem);
    const int tid = threadIdx.x;
    const int lane = tid & 31;
    const int w = tid >> 5;
    const int wm = w & 1;          // 2 row groups of 32
    const int wn = w >> 1;         // gate 0..3
    const int nt = blockIdx.x;
    const int mb = blockIdx.y * MT;

    const __half* xp = use_xd ? g_xd : (g_src + (size_t)t * CB * XSTR);
    const __half* hp = g_h[rd];

    // cp.async A mapping: 1024 granules of 16B, 4 per thread (stage 16KB)
    int ar[4], acg[4];
    uint32_t aoff[4];
#pragma unroll
    for (int it = 0; it < 4; ++it) {
        int idx = tid + it * 256;
        ar[it]  = idx >> 4;        // row 0..63
        acg[it] = idx & 15;        // 16B granule col 0..15
        aoff[it] = (uint32_t)(ar[it] * 256 + ((acg[it] ^ (ar[it] & 7)) << 4));
    }

    auto issue_chunk = [&](int ch, uint32_t buf) {
        const __half* p0;
        int stride, koff;
        if (ch < NCH_X) { p0 = xp; stride = XSTR; koff = ch * 128; }
        else            { p0 = hp; stride = CH;   koff = (ch - NCH_X) * 128; }
#pragma unroll
        for (int it = 0; it < 4; ++it) {
            const __half* sp = p0 + (size_t)(mb + ar[it]) * stride + koff + acg[it] * 8;
            CP16(buf + aoff[it], sp);
        }
    };

    // A ldsm base patterns (warp tile 32 rows x 32 cols)
    uint32_t abase[2]; int amask[2];
#pragma unroll
    for (int mg = 0; mg < 2; ++mg) {
        int rr = wm * 32 + mg * 16 + (lane & 15);
        abase[mg] = (uint32_t)(rr * 256);
        amask[mg] = rr & 7;
    }
    const int akc_half = lane >> 4;

    uint32_t ah[2][2][4];   // [buf][mg][regs]
    auto prefetch_A = [&](uint32_t buf, int fi, int b) {
        uint32_t g = (uint32_t)(2 * fi + akc_half);   // granule col 0..15
#pragma unroll
        for (int mg = 0; mg < 2; ++mg)
            ldsm4(ah[b][mg], buf + abase[mg] + ((g ^ (uint32_t)amask[mg]) << 4));
    };

    // W fragment pointer (uint4 units); flat f strides 64 uint4
    const uint4* wbase = g_Wfrag + ((size_t)(nt * 4 + wn) * NK16) * 64 + lane * 2;

    float acc[2][4][4];
#pragma unroll
    for (int mg = 0; mg < 2; ++mg)
#pragma unroll
        for (int nb = 0; nb < 4; ++nb)
#pragma unroll
            for (int e = 0; e < 4; ++e) acc[mg][nb][e] = 0.0f;

    // A prologue: 2 stages in flight
    issue_chunk(0, sb);        CP_COMMIT();
    issue_chunk(1, sb + ABUF); CP_COMMIT();

    // W prologue: ring slots 0..2 <- flat f 0..2
    uint4 wr0[4], wr1[4];
#pragma unroll
    for (int s = 0; s < 3; ++s) {
        const uint4* np = wbase + (size_t)s * 64;
        wr0[s] = __ldg(np); wr1[s] = __ldg(np + 1);
    }

#pragma unroll 1
    for (int ch = 0; ch < NCH; ++ch) {
        const uint32_t buf = sb + (uint32_t)(ch % 3) * ABUF;
        if (ch == NCH - 1) { CP_WAIT(0); } else { CP_WAIT(1); }   // chunk ch landed
        __syncthreads();   // all warps past chunk ch-1 compute; stage (ch+2)%3 free
        if (ch + 2 < NCH) issue_chunk(ch + 2, sb + (uint32_t)((ch + 2) % 3) * ABUF);
        CP_COMMIT();       // empty group ok

        prefetch_A(buf, 0, 0);
        int cur = 0;
#pragma unroll
        for (int fi = 0; fi < 8; ++fi) {
            const int f = ch * 8 + fi;
            // W prefetch f+3 into ring slot (f+3)&3
            if (f + 3 < NK16) {
                const uint4* np = wbase + (size_t)(f + 3) * 64;
                wr0[(f + 3) & 3] = __ldg(np);
                wr1[(f + 3) & 3] = __ldg(np + 1);
            }
            // A prefetch next k16 of this chunk
            if (fi < 7) prefetch_A(buf, fi + 1, cur ^ 1);

            const int ws = f & 3;
            uint32_t b0[4] = {wr0[ws].x, wr0[ws].z, wr1[ws].x, wr1[ws].z};
            uint32_t b1[4] = {wr0[ws].y, wr0[ws].w, wr1[ws].y, wr1[ws].w};
#pragma unroll
            for (int mg = 0; mg < 2; ++mg)
#pragma unroll
                for (int nb = 0; nb < 4; ++nb)
                    mma_h(acc[mg][nb], ah[cur][mg], b0[nb], b1[nb]);
            cur ^= 1;
        }
    }
    __syncthreads();   // all ldsm consumption done before sg overwrite

    // gate exchange (reuse smem): sg[4 gates * 64 rows][SGJ]
    float* sg = (float*)smem;
#pragma unroll
    for (int mg = 0; mg < 2; ++mg)
#pragma unroll
        for (int nb = 0; nb < 4; ++nb) {
            int r0 = wm * 32 + mg * 16 + (lane >> 2);
            int jj = nb * 8 + (lane & 3) * 2;
            float* p0 = &sg[((size_t)(wn * 64 + r0)) * SGJ + jj];
            p0[0] = acc[mg][nb][0]; p0[1] = acc[mg][nb][1];
            float* p1 = p0 + 8 * SGJ;
            p1[0] = acc[mg][nb][2]; p1[1] = acc[mg][nb][3];
        }
    __syncthreads();

    // cell update: 64 rows x 32 j -> 256 threads x (1 row, 8 j)
    {
        int row = tid >> 2;
        int j0 = (tid & 3) * 8;
        int jcol = nt * 32 + j0;
        size_t off = (size_t)(mb + row) * CH + jcol;

        float gv[4][8];
#pragma unroll
        for (int g = 0; g < 4; ++g) {
            const float* p = &sg[((size_t)(g * 64 + row)) * SGJ + j0];
#pragma unroll
            for (int e = 0; e < 8; ++e) gv[g][e] = p[e] + g_bias[g * CH + jcol + e];
        }
        float4 cA = *(const float4*)(g_c + off);
        float4 cB = *(const float4*)(g_c + off + 4);
        float cold[8] = {cA.x, cA.y, cA.z, cA.w, cB.x, cB.y, cB.z, cB.w};
        float cn[8], hn[8];
#pragma unroll
        for (int e = 0; e < 8; ++e) {
            float ci = sigf(gv[0][e]);
            float cf = sigf(gv[1][e]);
            float cg = tanhf(gv[2][e]);
            float co = sigf(gv[3][e]);
            cn[e] = cf * cold[e] + ci * cg;
            hn[e] = co * tanhf(cn[e]);
        }
        *(float4*)(g_c + off)     = make_float4(cn[0], cn[1], cn[2], cn[3]);
        *(float4*)(g_c + off + 4) = make_float4(cn[4], cn[5], cn[6], cn[7]);

        uint32_t ph[4];
#pragma unroll
        for (int e2 = 0; e2 < 4; ++e2) {
            __half ha = __float2half_rn(hn[e2 * 2]);
            __half hb = __float2half_rn(hn[e2 * 2 + 1]);
            ph[e2] = (uint32_t)__half_as_ushort(ha) | ((uint32_t)__half_as_ushort(hb) << 16);
        }
        *(uint4*)(&g_h[wr][off]) = make_uint4(ph[0], ph[1], ph[2], ph[3]);
    }
}

// ---------------- decoder projection ----------------
__global__ __launch_bounds__(256)
void proj_kernel(int hbuf,
                 const float* __restrict__ W_out,
                 const float* __restrict__ b_out,
                 float* __restrict__ outp)
{
    int lane = threadIdx.x & 31;
    int w = threadIdx.x >> 5;
    int d = blockIdx.x * 8 + w;
    int r0 = blockIdx.y * 8;
    const __half* hp = g_h[hbuf];
    int k0 = lane * 32;

    float wv[32];
    {
        const float4* wp = (const float4*)(W_out + (size_t)d * CH + k0);
#pragma unroll
        for (int q = 0; q < 8; ++q) {
            float4 f = wp[q];
            wv[q * 4 + 0] = f.x; wv[q * 4 + 1] = f.y; wv[q * 4 + 2] = f.z; wv[q * 4 + 3] = f.w;
        }
    }
    float acc[8];
#pragma unroll
    for (int r = 0; r < 8; ++r) {
        const uint4* hq = (const uint4*)(hp + (size_t)(r0 + r) * CH + k0);
        float s = 0.0f;
#pragma unroll
        for (int q = 0; q < 4; ++q) {
            uint4 hv = hq[q];
            const __half2* h2 = (const __half2*)&hv;
#pragma unroll
            for (int e = 0; e < 4; ++e) {
                float2 a = __half22float2(h2[e]);
                int kk = q * 8 + e * 2;
                s += a.x * wv[kk] + a.y * wv[kk + 1];
            }
        }
        acc[r] = s;
    }
#pragma unroll
    for (int r = 0; r < 8; ++r) {
#pragma unroll
        for (int off = 16; off > 0; off >>= 1)
            acc[r] += __shfl_xor_sync(0xFFFFFFFFu, acc[r], off);
    }
    if (lane == 0) {
        float bo = b_out[d];
#pragma unroll
        for (int r = 0; r < 8; ++r) {
            float y = acc[r] + bo;
            int row = r0 + r;
            outp[(size_t)row * CML * CD + d] = y;
            g_xd[(size_t)row * XSTR + d] = __float2half_rn(y);
        }
    }
}

extern "C" void kernel_launch(void* const* d_in, const int* in_sizes, int n_in,
                              void* d_out, int out_size)
{
    (void)in_sizes; (void)n_in; (void)out_size;
    const float* src   = (const float*)d_in[0];
    const float* W_ih  = (const float*)d_in[1];
    const float* W_hh  = (const float*)d_in[2];
    const float* b_ih  = (const float*)d_in[3];
    const float* b_hh  = (const float*)d_in[4];
    const float* W_out = (const float*)d_in[5];
    const float* b_out = (const float*)d_in[6];
    float* out = (float*)d_out;

    static int once = 0;
    if (!once) {
        cudaFuncSetAttribute(lstm_step, cudaFuncAttributeMaxDynamicSharedMemorySize, SMEM_STEP);
        once = 1;
    }

    init_kernel<<<(CB * CH + 255) / 256, 256>>>(b_ih, b_hh);
    {
        size_t tot = (size_t)CS * CB * XSTR;
        src_split_kernel<<<(unsigned)((tot + 255) / 256), 256>>>(src);
    }
    {
        int tot = NT * 4 * NK16 * 128;
        prep_w_kernel<<<(tot + 255) / 256, 256>>>(W_ih, W_hh);
    }

    dim3 sgrid(NT, CB / MT);   // 32 x 8 = 256 CTAs
    dim3 pgrid(27, CB / 8);    // 27 x 64

    int p = 0;
    for (int t = 0; t < CS; ++t) {
        lstm_step<<<sgrid, 256, SMEM_STEP>>>(0, t, p, p ^ 1);
        p ^= 1;
    }
    for (int s = 0; s < CML; ++s) {
        if (s == 0) lstm_step<<<sgrid, 256, SMEM_STEP>>>(0, CS - 1, p, p ^ 1);
        else        lstm_step<<<sgrid, 256, SMEM_STEP>>>(1, 0, p, p ^ 1);
        proj_kernel<<<pgrid, 256>>>(p ^ 1, W_out, b_out, out + (size_t)s * CD);
        p ^= 1;
    }
}

// round 13
// speedup vs baseline: 1.7376x; 1.0514x over previous
#include <cuda_runtime.h>
#include <cuda_fp16.h>
#include <math.h>
#include <stdint.h>

#define CB   512
#define CS   120
#define CD   216
#define CH   1024
#define CML  24

#define NCH   10        // 2 x-chunks (K 216->256 padded) + 8 h-chunks, K=128 each
#define NCH_X 2
#define NT    32        // N tiles of 128 cols (4 j-octets x 4 gates x 8 j)
#define MT    64        // M tile per CTA
#define XSTR  256       // padded x-plane stride
#define NK16  80        // flat k16 steps (16 x + 64 h)

// A staging: 64 rows x 128 cols fp16 = 16KB per stage, 3 stages
#define ABUF 16384
#define SMEM_STEP (3 * ABUF)   // 49152

// ---------------- device globals ----------------
// W in B-fragment layout: flat k16 f=0..79, uint4[ (nt*4+wn)*80 + f ][64]
// warp strip wn covers j's [nt*32+wn*8, +8) x 4 gates (octet nb = gate)
__device__ __align__(16) uint4 g_Wfrag[(size_t)NT * 4 * NK16 * 64];   // 10.5MB
__device__ __align__(16) __half g_src[(size_t)CS * CB * XSTR];
__device__ __align__(16) __half g_xd[(size_t)CB * XSTR];
__device__ __align__(16) __half g_h[2][(size_t)CB * CH];
__device__ float g_c[(size_t)CB * CH];
__device__ float g_bias[4 * CH];

// ---------------- helpers ----------------
__device__ __forceinline__ uint32_t smem_u32(const void* p) {
    uint32_t a;
    asm("{ .reg .u64 t; cvta.to.shared.u64 t, %1; cvt.u32.u64 %0, t; }" : "=r"(a) : "l"(p));
    return a;
}
__device__ __forceinline__ void ldsm4(uint32_t* r, uint32_t addr) {
    asm volatile("ldmatrix.sync.aligned.m8n8.x4.shared.b16 {%0,%1,%2,%3}, [%4];"
        : "=r"(r[0]), "=r"(r[1]), "=r"(r[2]), "=r"(r[3]) : "r"(addr));
}
__device__ __forceinline__ void mma_h(float* d, const uint32_t* a, uint32_t b0, uint32_t b1) {
    asm volatile("mma.sync.aligned.m16n8k16.row.col.f32.f16.f16.f32 "
        "{%0,%1,%2,%3}, {%4,%5,%6,%7}, {%8,%9}, {%0,%1,%2,%3};"
        : "+f"(d[0]), "+f"(d[1]), "+f"(d[2]), "+f"(d[3])
        : "r"(a[0]), "r"(a[1]), "r"(a[2]), "r"(a[3]), "r"(b0), "r"(b1));
}
#define CP16(dst, src) \
    asm volatile("cp.async.cg.shared.global [%0], [%1], 16;" :: "r"(dst), "l"(src))
#define CP_COMMIT() asm volatile("cp.async.commit_group;" ::: "memory")
#define CP_WAIT(n)  asm volatile("cp.async.wait_group %0;" :: "n"(n) : "memory")

__device__ __forceinline__ float sigf(float x) { return 1.0f / (1.0f + __expf(-x)); }

// ---------------- init / precompute ----------------
__global__ void init_kernel(const float* __restrict__ b_ih, const float* __restrict__ b_hh) {
    int idx = blockIdx.x * blockDim.x + threadIdx.x;
    if (idx < CB * CH) {
        g_c[idx] = 0.0f;
        g_h[0][idx] = __float2half_rn(0.0f);
    }
    if (idx < CB * XSTR) g_xd[idx] = __float2half_rn(0.0f);
    if (idx < 4 * CH) g_bias[idx] = b_ih[idx] + b_hh[idx];
}

__global__ void src_split_kernel(const float* __restrict__ src) {
    size_t idx = (size_t)blockIdx.x * blockDim.x + threadIdx.x;
    if (idx >= (size_t)CS * CB * XSTR) return;
    int c = (int)(idx & (XSTR - 1));
    int r = (int)((idx >> 8) & (CB - 1));
    int t = (int)(idx >> 17);
    float v = (c < CD) ? src[((size_t)r * CS + t) * CD + c] : 0.0f;
    g_src[idx] = __float2half_rn(v);
}

// W -> B-fragment layout (fp16), gate-interleaved N packing.
// Warp strip (nt, wn): octet nb = gate nb; col-in-octet = lane>>2 -> j = nt*32+wn*8+(lane>>2).
__global__ void prep_w_kernel(const float* __restrict__ W_ih, const float* __restrict__ W_hh) {
    int s = blockIdx.x * blockDim.x + threadIdx.x;
    const int TOT = NT * 4 * NK16 * 128;
    if (s >= TOT) return;
    int nb   = s & 3;          // octet = GATE
    int lane = (s >> 2) & 31;
    int rest = s >> 7;
    int f  = rest % NK16; rest /= NK16;   // flat k16 0..79
    int wn = rest & 3;                    // j-octet group
    int nt = rest >> 2;

    int j = nt * 32 + wn * 8 + (lane >> 2);
    int R = nb * CH + j;                  // gate-major weight row
    int k0 = f * 16 + (lane & 3) * 2;

    float v[4];
    if (f < 16) {
        int ks[4] = {k0, k0 + 1, k0 + 8, k0 + 9};
#pragma unroll
        for (int q = 0; q < 4; ++q)
            v[q] = (ks[q] < CD) ? W_ih[(size_t)R * CD + ks[q]] : 0.0f;
    } else {
        const float* wr = W_hh + (size_t)R * CH + (k0 - 256);
        v[0] = wr[0]; v[1] = wr[1]; v[2] = wr[8]; v[3] = wr[9];
    }
    uint32_t lo = (uint32_t)__half_as_ushort(__float2half_rn(v[0])) |
                  ((uint32_t)__half_as_ushort(__float2half_rn(v[1])) << 16);
    uint32_t hi = (uint32_t)__half_as_ushort(__float2half_rn(v[2])) |
                  ((uint32_t)__half_as_ushort(__float2half_rn(v[3])) << 16);
    size_t dest = (((size_t)(nt * 4 + wn) * NK16 + f)) * 128 + lane * 4 + nb;
    ((uint2*)g_Wfrag)[dest] = make_uint2(lo, hi);
}

// ---------------- fused LSTM step: K-chunk 128, in-register cell update ----------------
__global__ __launch_bounds__(256, 2)
void lstm_step(int use_xd, int t, int rd, int wr)
{
    extern __shared__ char smem[];
    const uint32_t sb = smem_u32(smem);
    const int tid = threadIdx.x;
    const int lane = tid & 31;
    const int w = tid >> 5;
    const int wm = w & 1;          // 2 row groups of 32
    const int wn = w >> 1;         // j-octet group 0..3
    const int nt = blockIdx.x;
    const int mb = blockIdx.y * MT;

    const __half* xp = use_xd ? g_xd : (g_src + (size_t)t * CB * XSTR);
    const __half* hp = g_h[rd];

    // cp.async A mapping: 1024 granules of 16B, 4 per thread (stage 16KB)
    int ar[4], acg[4];
    uint32_t aoff[4];
#pragma unroll
    for (int it = 0; it < 4; ++it) {
        int idx = tid + it * 256;
        ar[it]  = idx >> 4;        // row 0..63
        acg[it] = idx & 15;        // 16B granule col 0..15
        aoff[it] = (uint32_t)(ar[it] * 256 + ((acg[it] ^ (ar[it] & 7)) << 4));
    }

    auto issue_chunk = [&](int ch, uint32_t buf) {
        const __half* p0;
        int stride, koff;
        if (ch < NCH_X) { p0 = xp; stride = XSTR; koff = ch * 128; }
        else            { p0 = hp; stride = CH;   koff = (ch - NCH_X) * 128; }
#pragma unroll
        for (int it = 0; it < 4; ++it) {
            const __half* sp = p0 + (size_t)(mb + ar[it]) * stride + koff + acg[it] * 8;
            CP16(buf + aoff[it], sp);
        }
    };

    // A ldsm base patterns (warp tile 32 rows x 32 cols)
    uint32_t abase[2]; int amask[2];
#pragma unroll
    for (int mg = 0; mg < 2; ++mg) {
        int rr = wm * 32 + mg * 16 + (lane & 15);
        abase[mg] = (uint32_t)(rr * 256);
        amask[mg] = rr & 7;
    }
    const int akc_half = lane >> 4;

    uint32_t ah[2][2][4];   // [buf][mg][regs]
    auto prefetch_A = [&](uint32_t buf, int fi, int b) {
        uint32_t g = (uint32_t)(2 * fi + akc_half);
#pragma unroll
        for (int mg = 0; mg < 2; ++mg)
            ldsm4(ah[b][mg], buf + abase[mg] + ((g ^ (uint32_t)amask[mg]) << 4));
    };

    // W fragment pointer (uint4 units); flat f strides 64 uint4
    const uint4* wbase = g_Wfrag + ((size_t)(nt * 4 + wn) * NK16) * 64 + lane * 2;

    float acc[2][4][4];
#pragma unroll
    for (int mg = 0; mg < 2; ++mg)
#pragma unroll
        for (int nb = 0; nb < 4; ++nb)
#pragma unroll
            for (int e = 0; e < 4; ++e) acc[mg][nb][e] = 0.0f;

    // A prologue: 2 stages in flight
    issue_chunk(0, sb);        CP_COMMIT();
    issue_chunk(1, sb + ABUF); CP_COMMIT();

    // W prologue: ring slots 0..2 <- flat f 0..2
    uint4 wr0[4], wr1[4];
#pragma unroll
    for (int s = 0; s < 3; ++s) {
        const uint4* np = wbase + (size_t)s * 64;
        wr0[s] = __ldg(np); wr1[s] = __ldg(np + 1);
    }

#pragma unroll 1
    for (int ch = 0; ch < NCH; ++ch) {
        const uint32_t buf = sb + (uint32_t)(ch % 3) * ABUF;
        if (ch == NCH - 1) { CP_WAIT(0); } else { CP_WAIT(1); }
        __syncthreads();
        if (ch + 2 < NCH) issue_chunk(ch + 2, sb + (uint32_t)((ch + 2) % 3) * ABUF);
        CP_COMMIT();

        prefetch_A(buf, 0, 0);
        int cur = 0;
#pragma unroll
        for (int fi = 0; fi < 8; ++fi) {
            const int f = ch * 8 + fi;
            if (f + 3 < NK16) {
                const uint4* np = wbase + (size_t)(f + 3) * 64;
                wr0[(f + 3) & 3] = __ldg(np);
                wr1[(f + 3) & 3] = __ldg(np + 1);
            }
            if (fi < 7) prefetch_A(buf, fi + 1, cur ^ 1);

            const int ws = f & 3;
            uint32_t b0[4] = {wr0[ws].x, wr0[ws].z, wr1[ws].x, wr1[ws].z};
            uint32_t b1[4] = {wr0[ws].y, wr0[ws].w, wr1[ws].y, wr1[ws].w};
#pragma unroll
            for (int mg = 0; mg < 2; ++mg)
#pragma unroll
                for (int nb = 0; nb < 4; ++nb)
                    mma_h(acc[mg][nb], ah[cur][mg], b0[nb], b1[nb]);
            cur ^= 1;
        }
    }

    // ---- in-register cell update (no smem, no barriers) ----
    // acc[mg][gate][e]: e0=(r,j0) e1=(r,j1) e2=(r+8,j0) e3=(r+8,j1)
    // r = wm*32 + mg*16 + (lane>>2); j = nt*32 + wn*8 + (lane&3)*2 + jl
    {
        const int jbase = nt * 32 + wn * 8 + (lane & 3) * 2;
        float bias2[4][2];
#pragma unroll
        for (int g = 0; g < 4; ++g) {
            bias2[g][0] = g_bias[g * CH + jbase];
            bias2[g][1] = g_bias[g * CH + jbase + 1];
        }
        __half* hw = g_h[wr];
#pragma unroll
        for (int mg = 0; mg < 2; ++mg) {
#pragma unroll
            for (int half = 0; half < 2; ++half) {
                int row = mb + wm * 32 + mg * 16 + (lane >> 2) + half * 8;
                size_t off = (size_t)row * CH + jbase;
                float2 cc = *(const float2*)(g_c + off);
                float cold[2] = {cc.x, cc.y};
                float hn[2];
#pragma unroll
                for (int jl = 0; jl < 2; ++jl) {
                    int e = half * 2 + jl;
                    float gi = acc[mg][0][e] + bias2[0][jl];
                    float gf = acc[mg][1][e] + bias2[1][jl];
                    float gg = acc[mg][2][e] + bias2[2][jl];
                    float go = acc[mg][3][e] + bias2[3][jl];
                    float cn = sigf(gf) * cold[jl] + sigf(gi) * tanhf(gg);
                    hn[jl] = sigf(go) * tanhf(cn);
                    cold[jl] = cn;
                }
                *(float2*)(g_c + off) = make_float2(cold[0], cold[1]);
                uint32_t hp2 = (uint32_t)__half_as_ushort(__float2half_rn(hn[0])) |
                               ((uint32_t)__half_as_ushort(__float2half_rn(hn[1])) << 16);
                *(uint32_t*)(hw + off) = hp2;
            }
        }
    }
}

// ---------------- decoder projection ----------------
__global__ __launch_bounds__(256)
void proj_kernel(int hbuf,
                 const float* __restrict__ W_out,
                 const float* __restrict__ b_out,
                 float* __restrict__ outp)
{
    int lane = threadIdx.x & 31;
    int w = threadIdx.x >> 5;
    int d = blockIdx.x * 8 + w;
    int r0 = blockIdx.y * 8;
    const __half* hp = g_h[hbuf];
    int k0 = lane * 32;

    float wv[32];
    {
        const float4* wp = (const float4*)(W_out + (size_t)d * CH + k0);
#pragma unroll
        for (int q = 0; q < 8; ++q) {
            float4 f = wp[q];
            wv[q * 4 + 0] = f.x; wv[q * 4 + 1] = f.y; wv[q * 4 + 2] = f.z; wv[q * 4 + 3] = f.w;
        }
    }
    float acc[8];
#pragma unroll
    for (int r = 0; r < 8; ++r) {
        const uint4* hq = (const uint4*)(hp + (size_t)(r0 + r) * CH + k0);
        float s = 0.0f;
#pragma unroll
        for (int q = 0; q < 4; ++q) {
            uint4 hv = hq[q];
            const __half2* h2 = (const __half2*)&hv;
#pragma unroll
            for (int e = 0; e < 4; ++e) {
                float2 a = __half22float2(h2[e]);
                int kk = q * 8 + e * 2;
                s += a.x * wv[kk] + a.y * wv[kk + 1];
            }
        }
        acc[r] = s;
    }
#pragma unroll
    for (int r = 0; r < 8; ++r) {
#pragma unroll
        for (int off = 16; off > 0; off >>= 1)
            acc[r] += __shfl_xor_sync(0xFFFFFFFFu, acc[r], off);
    }
    if (lane == 0) {
        float bo = b_out[d];
#pragma unroll
        for (int r = 0; r < 8; ++r) {
            float y = acc[r] + bo;
            int row = r0 + r;
            outp[(size_t)row * CML * CD + d] = y;
            g_xd[(size_t)row * XSTR + d] = __float2half_rn(y);
        }
    }
}

extern "C" void kernel_launch(void* const* d_in, const int* in_sizes, int n_in,
                              void* d_out, int out_size)
{
    (void)in_sizes; (void)n_in; (void)out_size;
    const float* src   = (const float*)d_in[0];
    const float* W_ih  = (const float*)d_in[1];
    const float* W_hh  = (const float*)d_in[2];
    const float* b_ih  = (const float*)d_in[3];
    const float* b_hh  = (const float*)d_in[4];
    const float* W_out = (const float*)d_in[5];
    const float* b_out = (const float*)d_in[6];
    float* out = (float*)d_out;

    static int once = 0;
    if (!once) {
        cudaFuncSetAttribute(lstm_step, cudaFuncAttributeMaxDynamicSharedMemorySize, SMEM_STEP);
        once = 1;
    }

    init_kernel<<<(CB * CH + 255) / 256, 256>>>(b_ih, b_hh);
    {
        size_t tot = (size_t)CS * CB * XSTR;
        src_split_kernel<<<(unsigned)((tot + 255) / 256), 256>>>(src);
    }
    {
        int tot = NT * 4 * NK16 * 128;
        prep_w_kernel<<<(tot + 255) / 256, 256>>>(W_ih, W_hh);
    }

    dim3 sgrid(NT, CB / MT);   // 32 x 8 = 256 CTAs
    dim3 pgrid(27, CB / 8);    // 27 x 64

    int p = 0;
    for (int t = 0; t < CS; ++t) {
        lstm_step<<<sgrid, 256, SMEM_STEP>>>(0, t, p, p ^ 1);
        p ^= 1;
    }
    for (int s = 0; s < CML; ++s) {
        if (s == 0) lstm_step<<<sgrid, 256, SMEM_STEP>>>(0, CS - 1, p, p ^ 1);
        else        lstm_step<<<sgrid, 256, SMEM_STEP>>>(1, 0, p, p ^ 1);
        proj_kernel<<<pgrid, 256>>>(p ^ 1, W_out, b_out, out + (size_t)s * CD);
        p ^= 1;
    }
}